// round 11
// baseline (speedup 1.0000x reference)
#include <cuda_runtime.h>
#include <cfloat>
#include <cstdint>

// ---------------------------------------------------------------------------
// ResidualVQ on GB300 — round 6: tensor-core (tf32 mma.sync) approximate
// distance + exact fp32 re-check of a provably-sufficient shortlist.
//
// Exactness contract (unchanged bits vs round 5):
//   * enc / res / x / final out: ascending-k single-accumulator fmaf GEMMs
//   * exact dist for shortlisted codes: sequential ascending-c fmaf chain,
//     d = fadd(fsub(e2, fmul(2,dot)), cbn), lowest-index tie-break
//   * shortlist window W bounds tf32 conversion error (2^-10 ||a|| ||b|| per
//     dot, x2 for both candidates, x4 safety) + 256 abs slack for fp32
//     accumulation-order differences — exact argmin provably inside.
// ---------------------------------------------------------------------------

#define BM 128
#define BN 128
#define BK 16

#define MTOK 16384
#define TDIM 2048
#define DIN  768
#define RVQn 512
#define NQn  8
#define CSn  1024
#define CDn  256
#define DOUT 768

// scratch (device globals; no allocation allowed)
__device__ float g_x     [MTOK * RVQn];
__device__ float g_res   [MTOK * RVQn];
__device__ float g_enc   [MTOK * CDn];
__device__ float g_cbn   [NQn * CSn];
__device__ float g_cbnmax[NQn];
__device__ float g_wc    [NQn * CSn * RVQn];
__device__ float g_dist  [MTOK * CSn];        // approx distances (64 MB)
__device__ int   g_idx   [MTOK];

// shared-memory pool indexing for the fp32 GEMM
#define AS(b,k,m) SM[(b)*(BK*BM) + (k)*BM + (m)]
#define BS(b,k,n) SM[2*(BK*BM) + (b)*(BK*BN) + (k)*BN + (n)]

// ---------------------------------------------------------------------------
// Exact fp32 SGEMM (unchanged numerics): C[m,n] = sum_k A[m,k]*B[n,k]
// AMODE: 0 = A row-major; 1 = A is z (B,DIN,T) transposed view; 3 = A - A2.
// EPI:   0 = C = acc + bias (+ optional dup store C2)
//        2 = transposed store into (B, DOUT, T) with bias
//        3 = raw store C = acc
// ---------------------------------------------------------------------------
template<int AMODE, int EPI>
__global__ void __launch_bounds__(256, 2)
gemm_kernel(const float* __restrict__ A,
            const float* __restrict__ A2,
            const float* __restrict__ B,
            const float* __restrict__ bias,
            float* __restrict__ C,
            float* __restrict__ C2,
            int K, int N,
            size_t qsA, size_t qsB, size_t qsC)
{
    __shared__ float SM[2*BK*BM + 2*BK*BN];

    const int q = blockIdx.z;
    A += (size_t)q * qsA;
    B += (size_t)q * qsB;
    C += (size_t)q * qsC;

    const int tid = threadIdx.x;
    const int m0  = blockIdx.y * BM;
    const int n0  = blockIdx.x * BN;

    const int tx = tid & 15;
    const int ty = tid >> 4;
    const int arow = tid >> 2;
    const int acol = (tid & 3) << 2;

    const float* aptr0 = nullptr;
    const float* aptr1 = nullptr;
    if constexpr (AMODE == 0 || AMODE == 3) {
        aptr0 = A + (size_t)(m0 + arow) * K;
        aptr1 = A + (size_t)(m0 + arow + 64) * K;
    }
    const float* zb = nullptr;
    int t0z = 0, zk = 0, zm = 0;
    if constexpr (AMODE == 1) {
        const int b = m0 >> 11;
        t0z = m0 & (TDIM - 1);
        zb  = A + (size_t)b * DIN * TDIM;
        zk  = tid >> 5;
        zm  = (tid & 31) << 2;
    }
    const float* bptr0 = B + (size_t)(n0 + arow) * K;
    const float* bptr1 = B + (size_t)(n0 + arow + 64) * K;

    float4 ra0, ra1, rb0, rb1;

    auto load_tile = [&](int kt) {
        const int k0 = kt * BK;
        if constexpr (AMODE == 1) {
            ra0 = *reinterpret_cast<const float4*>(zb + (size_t)(k0 + zk)     * TDIM + t0z + zm);
            ra1 = *reinterpret_cast<const float4*>(zb + (size_t)(k0 + zk + 8) * TDIM + t0z + zm);
        } else {
            ra0 = *reinterpret_cast<const float4*>(aptr0 + k0 + acol);
            ra1 = *reinterpret_cast<const float4*>(aptr1 + k0 + acol);
            if constexpr (AMODE == 3) {
                float4 r0 = *reinterpret_cast<const float4*>(A2 + (size_t)(m0 + arow)      * K + k0 + acol);
                float4 r1 = *reinterpret_cast<const float4*>(A2 + (size_t)(m0 + arow + 64) * K + k0 + acol);
                ra0.x = __fsub_rn(ra0.x, r0.x); ra0.y = __fsub_rn(ra0.y, r0.y);
                ra0.z = __fsub_rn(ra0.z, r0.z); ra0.w = __fsub_rn(ra0.w, r0.w);
                ra1.x = __fsub_rn(ra1.x, r1.x); ra1.y = __fsub_rn(ra1.y, r1.y);
                ra1.z = __fsub_rn(ra1.z, r1.z); ra1.w = __fsub_rn(ra1.w, r1.w);
            }
        }
        rb0 = *reinterpret_cast<const float4*>(bptr0 + k0 + acol);
        rb1 = *reinterpret_cast<const float4*>(bptr1 + k0 + acol);
    };

    auto store_tile = [&](int b) {
        if constexpr (AMODE == 1) {
            *reinterpret_cast<float4*>(&AS(b, zk,     zm)) = ra0;
            *reinterpret_cast<float4*>(&AS(b, zk + 8, zm)) = ra1;
        } else {
            AS(b, acol + 0, arow) = ra0.x;
            AS(b, acol + 1, arow) = ra0.y;
            AS(b, acol + 2, arow) = ra0.z;
            AS(b, acol + 3, arow) = ra0.w;
            AS(b, acol + 0, arow + 64) = ra1.x;
            AS(b, acol + 1, arow + 64) = ra1.y;
            AS(b, acol + 2, arow + 64) = ra1.z;
            AS(b, acol + 3, arow + 64) = ra1.w;
        }
        BS(b, acol + 0, arow) = rb0.x;
        BS(b, acol + 1, arow) = rb0.y;
        BS(b, acol + 2, arow) = rb0.z;
        BS(b, acol + 3, arow) = rb0.w;
        BS(b, acol + 0, arow + 64) = rb1.x;
        BS(b, acol + 1, arow + 64) = rb1.y;
        BS(b, acol + 2, arow + 64) = rb1.z;
        BS(b, acol + 3, arow + 64) = rb1.w;
    };

    float acc[8][8];
#pragma unroll
    for (int i = 0; i < 8; ++i)
#pragma unroll
        for (int j = 0; j < 8; ++j) acc[i][j] = 0.f;

    auto compute = [&](int b) {
#pragma unroll
        for (int k = 0; k < BK; ++k) {
            float a[8], bq[8];
            *reinterpret_cast<float4*>(&a[0])  = *reinterpret_cast<const float4*>(&AS(b, k, ty * 4));
            *reinterpret_cast<float4*>(&a[4])  = *reinterpret_cast<const float4*>(&AS(b, k, 64 + ty * 4));
            *reinterpret_cast<float4*>(&bq[0]) = *reinterpret_cast<const float4*>(&BS(b, k, tx * 4));
            *reinterpret_cast<float4*>(&bq[4]) = *reinterpret_cast<const float4*>(&BS(b, k, 64 + tx * 4));
#pragma unroll
            for (int i = 0; i < 8; ++i)
#pragma unroll
                for (int j = 0; j < 8; ++j)
                    acc[i][j] = fmaf(a[i], bq[j], acc[i][j]);
        }
    };

    const int ntiles = K / BK;
    load_tile(0);
    store_tile(0);
    __syncthreads();
    int buf = 0;
    for (int kt = 0; kt < ntiles; ++kt) {
        const bool has_next = (kt + 1 < ntiles);
        if (has_next) load_tile(kt + 1);
        compute(buf);
        if (has_next) {
            store_tile(buf ^ 1);
            __syncthreads();
            buf ^= 1;
        }
    }

    int rows[8];
#pragma unroll
    for (int i = 0; i < 4; ++i) { rows[i] = ty * 4 + i; rows[i + 4] = 64 + ty * 4 + i; }

    if constexpr (EPI == 0 || EPI == 3) {
#pragma unroll
        for (int i = 0; i < 8; ++i) {
            const size_t r = (size_t)(m0 + rows[i]);
#pragma unroll
            for (int g = 0; g < 2; ++g) {
                const int c = n0 + (g ? 64 : 0) + tx * 4;
                float4 v;
                if constexpr (EPI == 0) {
                    const float4 bv = *reinterpret_cast<const float4*>(bias + c);
                    v.x = __fadd_rn(acc[i][g * 4 + 0], bv.x);
                    v.y = __fadd_rn(acc[i][g * 4 + 1], bv.y);
                    v.z = __fadd_rn(acc[i][g * 4 + 2], bv.z);
                    v.w = __fadd_rn(acc[i][g * 4 + 3], bv.w);
                } else {
                    v.x = acc[i][g * 4 + 0];
                    v.y = acc[i][g * 4 + 1];
                    v.z = acc[i][g * 4 + 2];
                    v.w = acc[i][g * 4 + 3];
                }
                *reinterpret_cast<float4*>(C + r * N + c) = v;
                if (EPI == 0 && C2) *reinterpret_cast<float4*>(C2 + r * N + c) = v;
            }
        }
    }

    if constexpr (EPI == 2) {
        float* Cs = &SM[0];
        const int b   = m0 >> 11;
        const int t0e = m0 & (TDIM - 1);
        __syncthreads();
#pragma unroll
        for (int s = 0; s < 4; ++s) {
            const int g = s >> 1;
            if ((tx >> 3) == (s & 1)) {
                const int cl = tx * 4 - 32 * (s & 1);
#pragma unroll
                for (int i = 0; i < 8; ++i)
#pragma unroll
                    for (int jj = 0; jj < 4; ++jj)
                        Cs[(cl + jj) * (BM + 4) + rows[i]] = acc[i][g * 4 + jj];
            }
            __syncthreads();
            for (int w = tid; w < 32 * BM; w += 256) {
                const int nl = w >> 7;
                const int tl = w & 127;
                const int n  = n0 + s * 32 + nl;
                C[((size_t)b * DOUT + n) * TDIM + t0e + tl] =
                    __fadd_rn(Cs[nl * (BM + 4) + tl], bias[n]);
            }
            __syncthreads();
        }
    }
}

// ---------------------------------------------------------------------------
// codebook row norms (exact sequential-ascending chain) — one launch
// ---------------------------------------------------------------------------
__global__ void __launch_bounds__(256)
cbnorm_all_kernel(const float* __restrict__ CB, float* __restrict__ out)
{
    __shared__ float s[32][CDn + 1];
    const int tid = threadIdx.x;
    const int r0  = blockIdx.x * 32;
    for (int i = tid; i < 32 * CDn; i += 256) {
        const int t = i >> 8;
        const int c = i & (CDn - 1);
        s[t][c] = CB[(size_t)(r0 + t) * CDn + c];
    }
    __syncthreads();
    if (tid < 32) {
        float acc = 0.f;
#pragma unroll 8
        for (int c = 0; c < CDn; ++c) {
            const float v = s[tid][c];
            acc = __fadd_rn(acc, __fmul_rn(v, v));
        }
        out[r0 + tid] = acc;
    }
}

// per-stage max codebook norm (for the shortlist window)
__global__ void __launch_bounds__(256)
cbnmax_kernel(const float* __restrict__ cbn, float* __restrict__ outmax)
{
    __shared__ float s[256];
    const int q = blockIdx.x;
    const int tid = threadIdx.x;
    float m = 0.f;
    for (int i = tid; i < CSn; i += 256) m = fmaxf(m, cbn[q * CSn + i]);
    s[tid] = m;
    __syncthreads();
    for (int o = 128; o; o >>= 1) {
        if (tid < o) s[tid] = fmaxf(s[tid], s[tid + o]);
        __syncthreads();
    }
    if (tid == 0) outmax[q] = s[0];
}

// ---------------------------------------------------------------------------
// tf32 helpers
// ---------------------------------------------------------------------------
__device__ __forceinline__ float f2tf32(float x)
{
    uint32_t u;
    asm("cvt.rna.tf32.f32 %0, %1;" : "=r"(u) : "f"(x));
    return __uint_as_float(u);
}

__device__ __forceinline__ void mma_tf32(float* d,
                                         uint32_t a0, uint32_t a1, uint32_t a2, uint32_t a3,
                                         uint32_t b0, uint32_t b1)
{
    asm volatile(
        "mma.sync.aligned.m16n8k8.row.col.f32.tf32.tf32.f32 "
        "{%0,%1,%2,%3}, {%4,%5,%6,%7}, {%8,%9}, {%0,%1,%2,%3};\n"
        : "+f"(d[0]), "+f"(d[1]), "+f"(d[2]), "+f"(d[3])
        : "r"(a0), "r"(a1), "r"(a2), "r"(a3), "r"(b0), "r"(b1));
}

// ---------------------------------------------------------------------------
// approx distance GEMM on tensor cores:
//   dtil[m][k] = cbn[k] - 2 * mma_tf32(enc[m,:], cb[k,:])
// CTA = 128 tokens x 128 codes; 8 warps in 4(m) x 2(n); warp tile 32x64.
// smem tiles k-major with stride 136 (conflict-free fragment loads).
// ---------------------------------------------------------------------------
#define BMP 136
#define TILEF (BK * BMP)          // 2176 floats per tile

__global__ void __launch_bounds__(256, 2)
dist_approx_kernel(const float* __restrict__ enc,
                   const float* __restrict__ cb,
                   const float* __restrict__ cbn,
                   float* __restrict__ dist)
{
    __shared__ float SMp[4 * TILEF];   // A x2 bufs, B x2 bufs (34.8 KB)

    const int tid   = threadIdx.x;
    const int m0    = blockIdx.x * BM;
    const int chunk = blockIdx.y;
    const int n0    = chunk * BN;

    const int w    = tid >> 5;         // warp 0..7
    const int lane = tid & 31;
    const int r    = lane >> 2;        // groupID 0..7
    const int c    = lane & 3;         // threadID_in_group 0..3
    const int wm0  = (w & 3) * 32;     // warp m offset
    const int wn0  = (w >> 2) * 64;    // warp n offset

    const int arow = tid >> 2;         // 0..63 (two passes)
    const int acol = (tid & 3) << 2;

    const float* aptr0 = enc + (size_t)(m0 + arow) * CDn;
    const float* aptr1 = enc + (size_t)(m0 + arow + 64) * CDn;
    const float* bptr0 = cb + (size_t)(n0 + arow) * CDn;
    const float* bptr1 = cb + (size_t)(n0 + arow + 64) * CDn;

    float4 ra0, ra1, rb0, rb1;
    auto load_tile = [&](int kt) {
        const int k0 = kt * BK;
        ra0 = *reinterpret_cast<const float4*>(aptr0 + k0 + acol);
        ra1 = *reinterpret_cast<const float4*>(aptr1 + k0 + acol);
        rb0 = *reinterpret_cast<const float4*>(bptr0 + k0 + acol);
        rb1 = *reinterpret_cast<const float4*>(bptr1 + k0 + acol);
    };
    auto store_tile = [&](int b) {
        float* Ab = SMp + b * TILEF;
        float* Bb = SMp + (2 + b) * TILEF;
        Ab[(acol + 0) * BMP + arow] = f2tf32(ra0.x);
        Ab[(acol + 1) * BMP + arow] = f2tf32(ra0.y);
        Ab[(acol + 2) * BMP + arow] = f2tf32(ra0.z);
        Ab[(acol + 3) * BMP + arow] = f2tf32(ra0.w);
        Ab[(acol + 0) * BMP + arow + 64] = f2tf32(ra1.x);
        Ab[(acol + 1) * BMP + arow + 64] = f2tf32(ra1.y);
        Ab[(acol + 2) * BMP + arow + 64] = f2tf32(ra1.z);
        Ab[(acol + 3) * BMP + arow + 64] = f2tf32(ra1.w);
        Bb[(acol + 0) * BMP + arow] = f2tf32(rb0.x);
        Bb[(acol + 1) * BMP + arow] = f2tf32(rb0.y);
        Bb[(acol + 2) * BMP + arow] = f2tf32(rb0.z);
        Bb[(acol + 3) * BMP + arow] = f2tf32(rb0.w);
        Bb[(acol + 0) * BMP + arow + 64] = f2tf32(rb1.x);
        Bb[(acol + 1) * BMP + arow + 64] = f2tf32(rb1.y);
        Bb[(acol + 2) * BMP + arow + 64] = f2tf32(rb1.z);
        Bb[(acol + 3) * BMP + arow + 64] = f2tf32(rb1.w);
    };

    float acc[2][8][4];
#pragma unroll
    for (int mt = 0; mt < 2; ++mt)
#pragma unroll
        for (int nt = 0; nt < 8; ++nt)
#pragma unroll
            for (int i = 0; i < 4; ++i) acc[mt][nt][i] = 0.f;

    auto compute = [&](int b) {
        const float* Ab = SMp + b * TILEF;
        const float* Bb = SMp + (2 + b) * TILEF;
#pragma unroll
        for (int k8 = 0; k8 < BK; k8 += 8) {
            uint32_t afr[2][4];
#pragma unroll
            for (int mt = 0; mt < 2; ++mt) {
                const int mb = wm0 + mt * 16 + r;
                afr[mt][0] = __float_as_uint(Ab[(k8 + c) * BMP + mb]);
                afr[mt][1] = __float_as_uint(Ab[(k8 + c) * BMP + mb + 8]);
                afr[mt][2] = __float_as_uint(Ab[(k8 + c + 4) * BMP + mb]);
                afr[mt][3] = __float_as_uint(Ab[(k8 + c + 4) * BMP + mb + 8]);
            }
#pragma unroll
            for (int nt = 0; nt < 8; ++nt) {
                const int nb = wn0 + nt * 8 + r;
                const uint32_t b0 = __float_as_uint(Bb[(k8 + c) * BMP + nb]);
                const uint32_t b1 = __float_as_uint(Bb[(k8 + c + 4) * BMP + nb]);
#pragma unroll
                for (int mt = 0; mt < 2; ++mt)
                    mma_tf32(acc[mt][nt], afr[mt][0], afr[mt][1], afr[mt][2], afr[mt][3], b0, b1);
            }
        }
    };

    const int ntiles = CDn / BK;       // 16
    load_tile(0);
    store_tile(0);
    __syncthreads();
    int buf = 0;
    for (int kt = 0; kt < ntiles; ++kt) {
        const bool has_next = (kt + 1 < ntiles);
        if (has_next) load_tile(kt + 1);
        compute(buf);
        if (has_next) {
            store_tile(buf ^ 1);
            __syncthreads();
            buf ^= 1;
        }
    }

    // epilogue: two 64-col slices staged through smem, apply cbn - 2*acc
    __syncthreads();
    float* P = SMp;                    // 128 x 64, stride 66 (needs 8448 <= 8704)
#pragma unroll
    for (int s = 0; s < 2; ++s) {
        if ((w >> 2) == s) {
#pragma unroll
            for (int mt = 0; mt < 2; ++mt) {
                const int row = wm0 + mt * 16 + r;
#pragma unroll
                for (int nt = 0; nt < 8; ++nt) {
                    const int col = nt * 8 + 2 * c;
                    P[row * 66 + col]           = acc[mt][nt][0];
                    P[row * 66 + col + 1]       = acc[mt][nt][1];
                    P[(row + 8) * 66 + col]     = acc[mt][nt][2];
                    P[(row + 8) * 66 + col + 1] = acc[mt][nt][3];
                }
            }
        }
        __syncthreads();
        const int c4 = (tid & 15) * 4;
        const int colg = n0 + s * 64 + c4;
        const float4 cn = *reinterpret_cast<const float4*>(cbn + colg);
#pragma unroll
        for (int j = 0; j < 8; ++j) {
            const int row = (tid >> 4) + j * 16;
            float4 v;
            v.x = __fsub_rn(cn.x, __fmul_rn(2.f, P[row * 66 + c4 + 0]));
            v.y = __fsub_rn(cn.y, __fmul_rn(2.f, P[row * 66 + c4 + 1]));
            v.z = __fsub_rn(cn.z, __fmul_rn(2.f, P[row * 66 + c4 + 2]));
            v.w = __fsub_rn(cn.w, __fmul_rn(2.f, P[row * 66 + c4 + 3]));
            *reinterpret_cast<float4*>(dist + (size_t)(m0 + row) * CSn + colg) = v;
        }
        __syncthreads();
    }
}

// ---------------------------------------------------------------------------
// scan + exact re-check. One warp per token:
//   1) min over the 1024 approx dists
//   2) exact e2 (sequential chain, lane 0)
//   3) every code within window W: exact dist (ascending-c fmaf chain,
//      exact assembly) -> argmin with lowest-index tie-break
// ---------------------------------------------------------------------------
__global__ void __launch_bounds__(256)
scan_recheck_kernel(const float* __restrict__ dist,
                    const float* __restrict__ enc,
                    const float* __restrict__ cb,
                    const float* __restrict__ cbn,
                    const float* __restrict__ cbnmax,
                    int* __restrict__ idxOut,
                    float* __restrict__ idxFloat)
{
    __shared__ float es[8][CDn];
    const int tid  = threadIdx.x;
    const int w    = tid >> 5;
    const int lane = tid & 31;
    const int m    = blockIdx.x * 8 + w;

    // load enc row to smem
    const float4* erow = reinterpret_cast<const float4*>(enc + (size_t)m * CDn);
#pragma unroll
    for (int i = 0; i < 2; ++i)
        *reinterpret_cast<float4*>(&es[w][lane * 4 + i * 128]) = erow[lane + i * 32];
    __syncwarp();

    // pass 1: row min of approx dists (keep values in regs)
    const float* drow = dist + (size_t)m * CSn;
    float dv[32];
    float bmin = FLT_MAX;
#pragma unroll
    for (int i = 0; i < 32; ++i) {
        dv[i] = drow[i * 32 + lane];
        bmin = fminf(bmin, dv[i]);
    }
#pragma unroll
    for (int o = 16; o; o >>= 1) bmin = fminf(bmin, __shfl_xor_sync(0xffffffffu, bmin, o));

    // exact e2 (sequential ascending chain) on lane 0
    float e2 = 0.f;
    if (lane == 0) {
        for (int ci = 0; ci < CDn; ++ci) {
            const float v = es[w][ci];
            e2 = __fadd_rn(e2, __fmul_rn(v, v));
        }
    }
    e2 = __shfl_sync(0xffffffffu, e2, 0);

    // window: 4x safety over the 2^-9 sqrt(e2*cbnmax) tf32 bound + abs slack
    const float W = sqrtf(e2) * sqrtf(cbnmax[0]) * (1.0f / 64.0f) + 256.0f;
    const float thr = bmin + W;

    float bd = FLT_MAX;
    int   bk = 0x7fffffff;
#pragma unroll 4
    for (int i = 0; i < 32; ++i) {
        if (dv[i] <= thr) {
            const int k = i * 32 + lane;
            const float4* crow = reinterpret_cast<const float4*>(cb + (size_t)k * CDn);
            float acc = 0.f;
#pragma unroll 4
            for (int c4 = 0; c4 < CDn / 4; ++c4) {
                const float4 cv = crow[c4];
                acc = fmaf(es[w][c4 * 4 + 0], cv.x, acc);
                acc = fmaf(es[w][c4 * 4 + 1], cv.y, acc);
                acc = fmaf(es[w][c4 * 4 + 2], cv.z, acc);
                acc = fmaf(es[w][c4 * 4 + 3], cv.w, acc);
            }
            const float d = __fadd_rn(__fsub_rn(e2, __fmul_rn(2.0f, acc)), cbn[k]);
            if (d < bd || (d == bd && k < bk)) { bd = d; bk = k; }
        }
    }
    // warp argmin reduce with lowest-index tie-break
#pragma unroll
    for (int o = 16; o; o >>= 1) {
        const float od = __shfl_xor_sync(0xffffffffu, bd, o);
        const int   ok = __shfl_xor_sync(0xffffffffu, bk, o);
        if (od < bd || (od == bd && ok < bk)) { bd = od; bk = ok; }
    }
    if (lane == 0) {
        idxOut[m] = bk;
        if (idxFloat) idxFloat[m] = (float)bk;
    }
}

// ---------------------------------------------------------------------------
// residual gather update: res[m][:] -= Wc[idx[m]][:] + out_b
// (rounding identical to the original GEMM epilogue)
// ---------------------------------------------------------------------------
__global__ void __launch_bounds__(256)
gather_update_kernel(const int*   __restrict__ idx,
                     const float* __restrict__ wc,
                     const float* __restrict__ ob,
                     float* __restrict__ res)
{
    const int warp = (blockIdx.x * blockDim.x + threadIdx.x) >> 5;
    const int lane = threadIdx.x & 31;
    const int m = warp;
    if (m >= MTOK) return;

    const int bi = idx[m];
    const float4* wrow = reinterpret_cast<const float4*>(wc + (size_t)bi * RVQn);
    const float4* brow = reinterpret_cast<const float4*>(ob);
    float4*       rrow = reinterpret_cast<float4*>(res + (size_t)m * RVQn);
#pragma unroll
    for (int i = lane; i < RVQn / 4; i += 32) {
        const float4 wv = wrow[i];
        const float4 bv = brow[i];
        float4 r = rrow[i];
        r.x = __fsub_rn(r.x, __fadd_rn(wv.x, bv.x));
        r.y = __fsub_rn(r.y, __fadd_rn(wv.y, bv.y));
        r.z = __fsub_rn(r.z, __fadd_rn(wv.z, bv.z));
        r.w = __fsub_rn(r.w, __fadd_rn(wv.w, bv.w));
        rrow[i] = r;
    }
}

// ---------------------------------------------------------------------------
// host launcher
// ---------------------------------------------------------------------------
extern "C" void kernel_launch(void* const* d_in, const int* in_sizes, int n_in,
                              void* d_out, int out_size)
{
    const float* z   = (const float*)d_in[0];
    const float* ipw = (const float*)d_in[1];
    const float* ipb = (const float*)d_in[2];
    const float* inw = (const float*)d_in[3];
    const float* inb = (const float*)d_in[4];
    const float* cbk = (const float*)d_in[5];
    const float* oww = (const float*)d_in[6];
    const float* owb = (const float*)d_in[7];
    const float* opw = (const float*)d_in[8];
    const float* opb = (const float*)d_in[9];
    float* outF = (float*)d_out;

    float *gx, *gres, *genc, *gcbn, *gcbnmax, *gwc, *gdist;
    int *gidx;
    cudaGetSymbolAddress((void**)&gx,      g_x);
    cudaGetSymbolAddress((void**)&gres,    g_res);
    cudaGetSymbolAddress((void**)&genc,    g_enc);
    cudaGetSymbolAddress((void**)&gcbn,    g_cbn);
    cudaGetSymbolAddress((void**)&gcbnmax, g_cbnmax);
    cudaGetSymbolAddress((void**)&gwc,     g_wc);
    cudaGetSymbolAddress((void**)&gdist,   g_dist);
    cudaGetSymbolAddress((void**)&gidx,    g_idx);

    const dim3 blk(256);
    const long long OUT0 = (long long)8 * DOUT * TDIM;
    const bool writeIdx = (long long)out_size >= OUT0 + (long long)NQn * MTOK;

    // 0. codebook norms + per-stage max, Wc precompute (one-time)
    cbnorm_all_kernel<<<NQn * CSn / 32, blk>>>(cbk, gcbn);
    cbnmax_kernel<<<NQn, blk>>>(gcbn, gcbnmax);
    gemm_kernel<0, 3><<<dim3(RVQn / BN, CSn / BM, NQn), blk>>>(
        cbk, nullptr, oww, nullptr, gwc, nullptr, CDn, RVQn,
        (size_t)CSn * CDn, (size_t)RVQn * CDn, (size_t)CSn * RVQn);

    // 1. input projection: x (and residual copy)
    gemm_kernel<1, 0><<<dim3(RVQn / BN, MTOK / BM), blk>>>(
        z, nullptr, ipw, ipb, gx, gres, DIN, RVQn, 0, 0, 0);

    // 2. RVQ stages
    for (int q = 0; q < NQn; ++q) {
        const float* cbq = cbk + (size_t)q * CSn * CDn;
        gemm_kernel<0, 0><<<dim3(CDn / BN, MTOK / BM), blk>>>(
            gres, nullptr,
            inw + (size_t)q * CDn * RVQn, inb + (size_t)q * CDn,
            genc, nullptr, RVQn, CDn, 0, 0, 0);
        dist_approx_kernel<<<dim3(MTOK / BM, CSn / BN), blk>>>(
            genc, cbq, gcbn + (size_t)q * CSn, gdist);
        float* idxF = writeIdx ? (outF + OUT0 + (size_t)q * MTOK) : nullptr;
        scan_recheck_kernel<<<MTOK / 8, blk>>>(
            gdist, genc, cbq, gcbn + (size_t)q * CSn, gcbnmax + q, gidx, idxF);
        gather_update_kernel<<<(MTOK * 32) / 256, blk>>>(
            gidx, gwc + (size_t)q * CSn * RVQn, owb + (size_t)q * RVQn, gres);
    }

    // 3. output projection on emb = x - res, transposed store
    gemm_kernel<3, 2><<<dim3(DOUT / BN, MTOK / BM), blk>>>(
        gx, gres, opw, opb, outF, nullptr, RVQn, DOUT, 0, 0, 0);
}

// round 16
// speedup vs baseline: 1.1054x; 1.1054x over previous
#include <cuda_runtime.h>
#include <cuda_fp16.h>
#include <cfloat>
#include <cstdint>

// ---------------------------------------------------------------------------
// ResidualVQ on GB300 — round 8: fp16 mma.sync (m16n8k16, legal at
// compute_103) approximate distance + exact fp32 re-check of a provably
// sufficient shortlist (scheme bit-validated in round 6).
// Exact path (enc/res/x/out GEMMs, e2, recheck rounding, tie-breaks) is byte
// identical to the passing round-5/6 kernels.
// ---------------------------------------------------------------------------

#define BM 128
#define BN 128
#define BK 16

#define MTOK 16384
#define TDIM 2048
#define DIN  768
#define RVQn 512
#define NQn  8
#define CSn  1024
#define CDn  256
#define DOUT 768

// scratch (device globals; no allocation allowed)
__device__ float  g_x     [MTOK * RVQn];
__device__ float  g_res   [MTOK * RVQn];
__device__ float  g_enc   [MTOK * CDn];
__device__ __half g_enc_h [MTOK * CDn];
__device__ __half g_cb_h  [NQn * CSn * CDn];
__device__ float  g_cbn   [NQn * CSn];
__device__ float  g_cbnmax[NQn];
__device__ float  g_wc    [NQn * CSn * RVQn];
__device__ float  g_dist  [MTOK * CSn];
__device__ int    g_idx   [MTOK];

// shared-memory pool indexing for the fp32 GEMM
#define AS(b,k,m) SM[(b)*(BK*BM) + (k)*BM + (m)]
#define BS(b,k,n) SM[2*(BK*BM) + (b)*(BK*BN) + (k)*BN + (n)]

// ---------------------------------------------------------------------------
// Exact fp32 SGEMM (unchanged numerics from passing kernels)
// ---------------------------------------------------------------------------
template<int AMODE, int EPI>
__global__ void __launch_bounds__(256, 2)
gemm_kernel(const float* __restrict__ A,
            const float* __restrict__ A2,
            const float* __restrict__ B,
            const float* __restrict__ bias,
            float* __restrict__ C,
            float* __restrict__ C2,
            int K, int N,
            size_t qsA, size_t qsB, size_t qsC)
{
    __shared__ float SM[2*BK*BM + 2*BK*BN];

    const int q = blockIdx.z;
    A += (size_t)q * qsA;
    B += (size_t)q * qsB;
    C += (size_t)q * qsC;

    const int tid = threadIdx.x;
    const int m0  = blockIdx.y * BM;
    const int n0  = blockIdx.x * BN;

    const int tx = tid & 15;
    const int ty = tid >> 4;
    const int arow = tid >> 2;
    const int acol = (tid & 3) << 2;

    const float* aptr0 = nullptr;
    const float* aptr1 = nullptr;
    if constexpr (AMODE == 0 || AMODE == 3) {
        aptr0 = A + (size_t)(m0 + arow) * K;
        aptr1 = A + (size_t)(m0 + arow + 64) * K;
    }
    const float* zb = nullptr;
    int t0z = 0, zk = 0, zm = 0;
    if constexpr (AMODE == 1) {
        const int b = m0 >> 11;
        t0z = m0 & (TDIM - 1);
        zb  = A + (size_t)b * DIN * TDIM;
        zk  = tid >> 5;
        zm  = (tid & 31) << 2;
    }
    const float* bptr0 = B + (size_t)(n0 + arow) * K;
    const float* bptr1 = B + (size_t)(n0 + arow + 64) * K;

    float4 ra0, ra1, rb0, rb1;

    auto load_tile = [&](int kt) {
        const int k0 = kt * BK;
        if constexpr (AMODE == 1) {
            ra0 = *reinterpret_cast<const float4*>(zb + (size_t)(k0 + zk)     * TDIM + t0z + zm);
            ra1 = *reinterpret_cast<const float4*>(zb + (size_t)(k0 + zk + 8) * TDIM + t0z + zm);
        } else {
            ra0 = *reinterpret_cast<const float4*>(aptr0 + k0 + acol);
            ra1 = *reinterpret_cast<const float4*>(aptr1 + k0 + acol);
            if constexpr (AMODE == 3) {
                float4 r0 = *reinterpret_cast<const float4*>(A2 + (size_t)(m0 + arow)      * K + k0 + acol);
                float4 r1 = *reinterpret_cast<const float4*>(A2 + (size_t)(m0 + arow + 64) * K + k0 + acol);
                ra0.x = __fsub_rn(ra0.x, r0.x); ra0.y = __fsub_rn(ra0.y, r0.y);
                ra0.z = __fsub_rn(ra0.z, r0.z); ra0.w = __fsub_rn(ra0.w, r0.w);
                ra1.x = __fsub_rn(ra1.x, r1.x); ra1.y = __fsub_rn(ra1.y, r1.y);
                ra1.z = __fsub_rn(ra1.z, r1.z); ra1.w = __fsub_rn(ra1.w, r1.w);
            }
        }
        rb0 = *reinterpret_cast<const float4*>(bptr0 + k0 + acol);
        rb1 = *reinterpret_cast<const float4*>(bptr1 + k0 + acol);
    };

    auto store_tile = [&](int b) {
        if constexpr (AMODE == 1) {
            *reinterpret_cast<float4*>(&AS(b, zk,     zm)) = ra0;
            *reinterpret_cast<float4*>(&AS(b, zk + 8, zm)) = ra1;
        } else {
            AS(b, acol + 0, arow) = ra0.x;
            AS(b, acol + 1, arow) = ra0.y;
            AS(b, acol + 2, arow) = ra0.z;
            AS(b, acol + 3, arow) = ra0.w;
            AS(b, acol + 0, arow + 64) = ra1.x;
            AS(b, acol + 1, arow + 64) = ra1.y;
            AS(b, acol + 2, arow + 64) = ra1.z;
            AS(b, acol + 3, arow + 64) = ra1.w;
        }
        BS(b, acol + 0, arow) = rb0.x;
        BS(b, acol + 1, arow) = rb0.y;
        BS(b, acol + 2, arow) = rb0.z;
        BS(b, acol + 3, arow) = rb0.w;
        BS(b, acol + 0, arow + 64) = rb1.x;
        BS(b, acol + 1, arow + 64) = rb1.y;
        BS(b, acol + 2, arow + 64) = rb1.z;
        BS(b, acol + 3, arow + 64) = rb1.w;
    };

    float acc[8][8];
#pragma unroll
    for (int i = 0; i < 8; ++i)
#pragma unroll
        for (int j = 0; j < 8; ++j) acc[i][j] = 0.f;

    auto compute = [&](int b) {
#pragma unroll
        for (int k = 0; k < BK; ++k) {
            float a[8], bq[8];
            *reinterpret_cast<float4*>(&a[0])  = *reinterpret_cast<const float4*>(&AS(b, k, ty * 4));
            *reinterpret_cast<float4*>(&a[4])  = *reinterpret_cast<const float4*>(&AS(b, k, 64 + ty * 4));
            *reinterpret_cast<float4*>(&bq[0]) = *reinterpret_cast<const float4*>(&BS(b, k, tx * 4));
            *reinterpret_cast<float4*>(&bq[4]) = *reinterpret_cast<const float4*>(&BS(b, k, 64 + tx * 4));
#pragma unroll
            for (int i = 0; i < 8; ++i)
#pragma unroll
                for (int j = 0; j < 8; ++j)
                    acc[i][j] = fmaf(a[i], bq[j], acc[i][j]);
        }
    };

    const int ntiles = K / BK;
    load_tile(0);
    store_tile(0);
    __syncthreads();
    int buf = 0;
    for (int kt = 0; kt < ntiles; ++kt) {
        const bool has_next = (kt + 1 < ntiles);
        if (has_next) load_tile(kt + 1);
        compute(buf);
        if (has_next) {
            store_tile(buf ^ 1);
            __syncthreads();
            buf ^= 1;
        }
    }

    int rows[8];
#pragma unroll
    for (int i = 0; i < 4; ++i) { rows[i] = ty * 4 + i; rows[i + 4] = 64 + ty * 4 + i; }

    if constexpr (EPI == 0 || EPI == 3) {
#pragma unroll
        for (int i = 0; i < 8; ++i) {
            const size_t r = (size_t)(m0 + rows[i]);
#pragma unroll
            for (int g = 0; g < 2; ++g) {
                const int c = n0 + (g ? 64 : 0) + tx * 4;
                float4 v;
                if constexpr (EPI == 0) {
                    const float4 bv = *reinterpret_cast<const float4*>(bias + c);
                    v.x = __fadd_rn(acc[i][g * 4 + 0], bv.x);
                    v.y = __fadd_rn(acc[i][g * 4 + 1], bv.y);
                    v.z = __fadd_rn(acc[i][g * 4 + 2], bv.z);
                    v.w = __fadd_rn(acc[i][g * 4 + 3], bv.w);
                } else {
                    v.x = acc[i][g * 4 + 0];
                    v.y = acc[i][g * 4 + 1];
                    v.z = acc[i][g * 4 + 2];
                    v.w = acc[i][g * 4 + 3];
                }
                *reinterpret_cast<float4*>(C + r * N + c) = v;
                if (EPI == 0 && C2) *reinterpret_cast<float4*>(C2 + r * N + c) = v;
            }
        }
    }

    if constexpr (EPI == 2) {
        float* Cs = &SM[0];
        const int b   = m0 >> 11;
        const int t0e = m0 & (TDIM - 1);
        __syncthreads();
#pragma unroll
        for (int s = 0; s < 4; ++s) {
            const int g = s >> 1;
            if ((tx >> 3) == (s & 1)) {
                const int cl = tx * 4 - 32 * (s & 1);
#pragma unroll
                for (int i = 0; i < 8; ++i)
#pragma unroll
                    for (int jj = 0; jj < 4; ++jj)
                        Cs[(cl + jj) * (BM + 4) + rows[i]] = acc[i][g * 4 + jj];
            }
            __syncthreads();
            for (int w = tid; w < 32 * BM; w += 256) {
                const int nl = w >> 7;
                const int tl = w & 127;
                const int n  = n0 + s * 32 + nl;
                C[((size_t)b * DOUT + n) * TDIM + t0e + tl] =
                    __fadd_rn(Cs[nl * (BM + 4) + tl], bias[n]);
            }
            __syncthreads();
        }
    }
}

// ---------------------------------------------------------------------------
// codebook row norms (exact sequential-ascending chain)
// ---------------------------------------------------------------------------
__global__ void __launch_bounds__(256)
cbnorm_all_kernel(const float* __restrict__ CB, float* __restrict__ out)
{
    __shared__ float s[32][CDn + 1];
    const int tid = threadIdx.x;
    const int r0  = blockIdx.x * 32;
    for (int i = tid; i < 32 * CDn; i += 256) {
        const int t = i >> 8;
        const int c = i & (CDn - 1);
        s[t][c] = CB[(size_t)(r0 + t) * CDn + c];
    }
    __syncthreads();
    if (tid < 32) {
        float acc = 0.f;
#pragma unroll 8
        for (int c = 0; c < CDn; ++c) {
            const float v = s[tid][c];
            acc = __fadd_rn(acc, __fmul_rn(v, v));
        }
        out[r0 + tid] = acc;
    }
}

__global__ void __launch_bounds__(256)
cbnmax_kernel(const float* __restrict__ cbn, float* __restrict__ outmax)
{
    __shared__ float s[256];
    const int q = blockIdx.x;
    const int tid = threadIdx.x;
    float m = 0.f;
    for (int i = tid; i < CSn; i += 256) m = fmaxf(m, cbn[q * CSn + i]);
    s[tid] = m;
    __syncthreads();
    for (int o = 128; o; o >>= 1) {
        if (tid < o) s[tid] = fmaxf(s[tid], s[tid + o]);
        __syncthreads();
    }
    if (tid == 0) outmax[q] = s[0];
}

// ---------------------------------------------------------------------------
// fp32 -> fp16 conversion (8 elements per thread)
// ---------------------------------------------------------------------------
__global__ void __launch_bounds__(256)
cvt_half_kernel(const float* __restrict__ src, __half* __restrict__ dst, int n8)
{
    const int i = blockIdx.x * blockDim.x + threadIdx.x;
    if (i >= n8) return;
    const float4* s = reinterpret_cast<const float4*>(src) + (size_t)i * 2;
    const float4 a = s[0], b = s[1];
    __half2 p0 = __floats2half2_rn(a.x, a.y);
    __half2 p1 = __floats2half2_rn(a.z, a.w);
    __half2 p2 = __floats2half2_rn(b.x, b.y);
    __half2 p3 = __floats2half2_rn(b.z, b.w);
    uint4 o;
    o.x = *reinterpret_cast<uint32_t*>(&p0);
    o.y = *reinterpret_cast<uint32_t*>(&p1);
    o.z = *reinterpret_cast<uint32_t*>(&p2);
    o.w = *reinterpret_cast<uint32_t*>(&p3);
    reinterpret_cast<uint4*>(dst)[i] = o;
}

// ---------------------------------------------------------------------------
// fp16 mma helpers (legal at compute_103: ldmatrix sm_75+, mma fp16 sm_70+)
// ---------------------------------------------------------------------------
__device__ __forceinline__ uint32_t smem_u32(const void* p)
{
    uint32_t a;
    asm("{ .reg .u64 t; cvta.to.shared.u64 t, %1; cvt.u32.u64 %0, t; }"
        : "=r"(a) : "l"(p));
    return a;
}

__device__ __forceinline__ void ldmatrix_x4(uint32_t* r, uint32_t addr)
{
    asm volatile("ldmatrix.sync.aligned.m8n8.x4.shared.b16 {%0,%1,%2,%3}, [%4];"
                 : "=r"(r[0]), "=r"(r[1]), "=r"(r[2]), "=r"(r[3]) : "r"(addr));
}

__device__ __forceinline__ void mma16816(float* d, const uint32_t* a,
                                         uint32_t b0, uint32_t b1)
{
    asm volatile(
        "mma.sync.aligned.m16n8k16.row.col.f32.f16.f16.f32 "
        "{%0,%1,%2,%3}, {%4,%5,%6,%7}, {%8,%9}, {%0,%1,%2,%3};\n"
        : "+f"(d[0]), "+f"(d[1]), "+f"(d[2]), "+f"(d[3])
        : "r"(a[0]), "r"(a[1]), "r"(a[2]), "r"(a[3]), "r"(b0), "r"(b1));
}

// dist_fp16 smem: A tile 128 x 264 halves, B tile same (pad 8 halves = 16 B)
#define DH_PAD 264
#define DH_TILE_B (128 * DH_PAD * 2)          // 67584 bytes
#define DH_TOTAL  (2 * DH_TILE_B)             // 135168 bytes

// ---------------------------------------------------------------------------
// fp16 tensor-core approximate distance:
//   dist[m][k] = cbn[k] - 2 * fp16dot(enc[m,:], cb[k,:])   (fp32 accumulate)
// CTA = 128 tokens x 128 codes, K = 256 loaded once. 8 warps in 4(m) x 2(n),
// warp tile 32x64. Fragments via ldmatrix (B stored [code][k] row-major ->
// plain ldmatrix yields the col-major kxn fragment).
// ---------------------------------------------------------------------------
__global__ void __launch_bounds__(256)
dist_fp16_kernel(const __half* __restrict__ enc_h,
                 const __half* __restrict__ cb_h,
                 const float* __restrict__ cbn,
                 float* __restrict__ dist)
{
    extern __shared__ char dsm[];
    __half* Ah = reinterpret_cast<__half*>(dsm);
    __half* Bh = reinterpret_cast<__half*>(dsm + DH_TILE_B);

    const int tid  = threadIdx.x;
    const int m0   = blockIdx.x * BM;
    const int n0   = blockIdx.y * BN;
    const int w    = tid >> 5;
    const int lane = tid & 31;
    const int wm   = (w & 3) * 32;
    const int wn   = (w >> 2) * 64;

    // load A (enc) and B (cb) fp16 tiles, row-major with pad
#pragma unroll
    for (int it = 0; it < 16; ++it) {
        const int cid = it * 256 + tid;        // 4096 chunks of 8 halves
        const int row = cid >> 5;
        const int c8  = cid & 31;
        *reinterpret_cast<uint4*>(&Ah[row * DH_PAD + c8 * 8]) =
            reinterpret_cast<const uint4*>(enc_h + (size_t)(m0 + row) * CDn)[c8];
        *reinterpret_cast<uint4*>(&Bh[row * DH_PAD + c8 * 8]) =
            reinterpret_cast<const uint4*>(cb_h + (size_t)(n0 + row) * CDn)[c8];
    }
    __syncthreads();

    float acc[2][8][4];
#pragma unroll
    for (int mt = 0; mt < 2; ++mt)
#pragma unroll
        for (int nt = 0; nt < 8; ++nt)
#pragma unroll
            for (int i = 0; i < 4; ++i) acc[mt][nt][i] = 0.f;

    // ldmatrix lane roles: j = matrix index, r = row within matrix
    const int j = lane >> 3;
    const int r = lane & 7;
    const uint32_t a_base = smem_u32(Ah);
    const uint32_t b_base = smem_u32(Bh);
    // per-lane row/k offsets (halves): row += (j&1)*8 + r, k += (j>>1)*8
    const int lrow = (j & 1) * 8 + r;
    const int lk   = (j >> 1) * 8;

#pragma unroll
    for (int ks = 0; ks < 16; ++ks) {
        const int k0 = ks * 16;
        uint32_t afr[2][4];
#pragma unroll
        for (int mt = 0; mt < 2; ++mt) {
            const uint32_t addr = a_base +
                ((uint32_t)(wm + mt * 16 + lrow) * DH_PAD + k0 + lk) * 2u;
            ldmatrix_x4(afr[mt], addr);
        }
#pragma unroll
        for (int np = 0; np < 4; ++np) {
            uint32_t b4[4];
            const uint32_t addr = b_base +
                ((uint32_t)(wn + np * 16 + lrow) * DH_PAD + k0 + lk) * 2u;
            ldmatrix_x4(b4, addr);
            // matrices: j0 = codes +0-7 @k0, j1 = +8-15 @k0, j2 = +0-7 @k0+8, j3 = +8-15 @k0+8
            mma16816(acc[0][np * 2 + 0], afr[0], b4[0], b4[2]);
            mma16816(acc[0][np * 2 + 1], afr[0], b4[1], b4[3]);
            mma16816(acc[1][np * 2 + 0], afr[1], b4[0], b4[2]);
            mma16816(acc[1][np * 2 + 1], afr[1], b4[1], b4[3]);
        }
    }

    // epilogue (identical structure to the round-6 passing kernel):
    // stage 64-col slices in smem, apply cbn - 2*acc, store coalesced.
    __syncthreads();
    float* P = reinterpret_cast<float*>(dsm);     // 128 x 64, stride 66
    const int rg = lane >> 2;                     // d-fragment groupID
    const int cg = lane & 3;
#pragma unroll
    for (int s = 0; s < 2; ++s) {
        if ((w >> 2) == s) {
#pragma unroll
            for (int mt = 0; mt < 2; ++mt) {
                const int row = wm + mt * 16 + rg;
#pragma unroll
                for (int nt = 0; nt < 8; ++nt) {
                    const int col = nt * 8 + 2 * cg;
                    P[row * 66 + col]           = acc[mt][nt][0];
                    P[row * 66 + col + 1]       = acc[mt][nt][1];
                    P[(row + 8) * 66 + col]     = acc[mt][nt][2];
                    P[(row + 8) * 66 + col + 1] = acc[mt][nt][3];
                }
            }
        }
        __syncthreads();
        const int c4 = (tid & 15) * 4;
        const int colg = n0 + s * 64 + c4;
        const float4 cn = *reinterpret_cast<const float4*>(cbn + colg);
#pragma unroll
        for (int jj = 0; jj < 8; ++jj) {
            const int row = (tid >> 4) + jj * 16;
            float4 v;
            v.x = __fsub_rn(cn.x, __fmul_rn(2.f, P[row * 66 + c4 + 0]));
            v.y = __fsub_rn(cn.y, __fmul_rn(2.f, P[row * 66 + c4 + 1]));
            v.z = __fsub_rn(cn.z, __fmul_rn(2.f, P[row * 66 + c4 + 2]));
            v.w = __fsub_rn(cn.w, __fmul_rn(2.f, P[row * 66 + c4 + 3]));
            *reinterpret_cast<float4*>(dist + (size_t)(m0 + row) * CSn + colg) = v;
        }
        __syncthreads();
    }
}

// ---------------------------------------------------------------------------
// scan + exact re-check (validated bit-exact in round 6, window unchanged:
// fp16 conversion error <= tf32's, so the same bound holds):
//   shortlist = { k : dtil[k] <= min(dtil) + W },
//   W = sqrt(e2)*sqrt(cbnmax)/64 + 256
// exact d = fadd(fsub(e2, fmul(2, dot)), cbn), ascending-c fmaf chain.
// ---------------------------------------------------------------------------
__global__ void __launch_bounds__(256)
scan_recheck_kernel(const float* __restrict__ dist,
                    const float* __restrict__ enc,
                    const float* __restrict__ cb,
                    const float* __restrict__ cbn,
                    const float* __restrict__ cbnmax,
                    int* __restrict__ idxOut,
                    float* __restrict__ idxFloat)
{
    __shared__ float es[8][CDn];
    const int tid  = threadIdx.x;
    const int w    = tid >> 5;
    const int lane = tid & 31;
    const int m    = blockIdx.x * 8 + w;

    const float4* erow = reinterpret_cast<const float4*>(enc + (size_t)m * CDn);
#pragma unroll
    for (int i = 0; i < 2; ++i)
        *reinterpret_cast<float4*>(&es[w][lane * 4 + i * 128]) = erow[lane + i * 32];
    __syncwarp();

    const float* drow = dist + (size_t)m * CSn;
    float dv[32];
    float bmin = FLT_MAX;
#pragma unroll
    for (int i = 0; i < 32; ++i) {
        dv[i] = drow[i * 32 + lane];
        bmin = fminf(bmin, dv[i]);
    }
#pragma unroll
    for (int o = 16; o; o >>= 1) bmin = fminf(bmin, __shfl_xor_sync(0xffffffffu, bmin, o));

    float e2 = 0.f;
    if (lane == 0) {
        for (int ci = 0; ci < CDn; ++ci) {
            const float v = es[w][ci];
            e2 = __fadd_rn(e2, __fmul_rn(v, v));
        }
    }
    e2 = __shfl_sync(0xffffffffu, e2, 0);

    const float W = sqrtf(e2) * sqrtf(cbnmax[0]) * (1.0f / 64.0f) + 256.0f;
    const float thr = bmin + W;

    float bd = FLT_MAX;
    int   bk = 0x7fffffff;
#pragma unroll 4
    for (int i = 0; i < 32; ++i) {
        if (dv[i] <= thr) {
            const int k = i * 32 + lane;
            const float4* crow = reinterpret_cast<const float4*>(cb + (size_t)k * CDn);
            float acc = 0.f;
#pragma unroll 4
            for (int c4 = 0; c4 < CDn / 4; ++c4) {
                const float4 cv = crow[c4];
                acc = fmaf(es[w][c4 * 4 + 0], cv.x, acc);
                acc = fmaf(es[w][c4 * 4 + 1], cv.y, acc);
                acc = fmaf(es[w][c4 * 4 + 2], cv.z, acc);
                acc = fmaf(es[w][c4 * 4 + 3], cv.w, acc);
            }
            const float d = __fadd_rn(__fsub_rn(e2, __fmul_rn(2.0f, acc)), cbn[k]);
            if (d < bd || (d == bd && k < bk)) { bd = d; bk = k; }
        }
    }
#pragma unroll
    for (int o = 16; o; o >>= 1) {
        const float od = __shfl_xor_sync(0xffffffffu, bd, o);
        const int   ok = __shfl_xor_sync(0xffffffffu, bk, o);
        if (od < bd || (od == bd && ok < bk)) { bd = od; bk = ok; }
    }
    if (lane == 0) {
        idxOut[m] = bk;
        if (idxFloat) idxFloat[m] = (float)bk;
    }
}

// ---------------------------------------------------------------------------
// residual gather update: res[m][:] -= Wc[idx[m]][:] + out_b  (exact epilogue)
// ---------------------------------------------------------------------------
__global__ void __launch_bounds__(256)
gather_update_kernel(const int*   __restrict__ idx,
                     const float* __restrict__ wc,
                     const float* __restrict__ ob,
                     float* __restrict__ res)
{
    const int warp = (blockIdx.x * blockDim.x + threadIdx.x) >> 5;
    const int lane = threadIdx.x & 31;
    const int m = warp;
    if (m >= MTOK) return;

    const int bi = idx[m];
    const float4* wrow = reinterpret_cast<const float4*>(wc + (size_t)bi * RVQn);
    const float4* brow = reinterpret_cast<const float4*>(ob);
    float4*       rrow = reinterpret_cast<float4*>(res + (size_t)m * RVQn);
#pragma unroll
    for (int i = lane; i < RVQn / 4; i += 32) {
        const float4 wv = wrow[i];
        const float4 bv = brow[i];
        float4 r = rrow[i];
        r.x = __fsub_rn(r.x, __fadd_rn(wv.x, bv.x));
        r.y = __fsub_rn(r.y, __fadd_rn(wv.y, bv.y));
        r.z = __fsub_rn(r.z, __fadd_rn(wv.z, bv.z));
        r.w = __fsub_rn(r.w, __fadd_rn(wv.w, bv.w));
        rrow[i] = r;
    }
}

// ---------------------------------------------------------------------------
// host launcher
// ---------------------------------------------------------------------------
extern "C" void kernel_launch(void* const* d_in, const int* in_sizes, int n_in,
                              void* d_out, int out_size)
{
    const float* z   = (const float*)d_in[0];
    const float* ipw = (const float*)d_in[1];
    const float* ipb = (const float*)d_in[2];
    const float* inw = (const float*)d_in[3];
    const float* inb = (const float*)d_in[4];
    const float* cbk = (const float*)d_in[5];
    const float* oww = (const float*)d_in[6];
    const float* owb = (const float*)d_in[7];
    const float* opw = (const float*)d_in[8];
    const float* opb = (const float*)d_in[9];
    float* outF = (float*)d_out;

    float *gx, *gres, *genc, *gcbn, *gcbnmax, *gwc, *gdist;
    __half *gench, *gcbh;
    int *gidx;
    cudaGetSymbolAddress((void**)&gx,      g_x);
    cudaGetSymbolAddress((void**)&gres,    g_res);
    cudaGetSymbolAddress((void**)&genc,    g_enc);
    cudaGetSymbolAddress((void**)&gench,   g_enc_h);
    cudaGetSymbolAddress((void**)&gcbh,    g_cb_h);
    cudaGetSymbolAddress((void**)&gcbn,    g_cbn);
    cudaGetSymbolAddress((void**)&gcbnmax, g_cbnmax);
    cudaGetSymbolAddress((void**)&gwc,     g_wc);
    cudaGetSymbolAddress((void**)&gdist,   g_dist);
    cudaGetSymbolAddress((void**)&gidx,    g_idx);

    cudaFuncSetAttribute(dist_fp16_kernel,
                         cudaFuncAttributeMaxDynamicSharedMemorySize, DH_TOTAL);

    const dim3 blk(256);
    const long long OUT0 = (long long)8 * DOUT * TDIM;
    const bool writeIdx = (long long)out_size >= OUT0 + (long long)NQn * MTOK;

    // 0. codebook norms/max, fp16 codebooks, Wc precompute (one-time)
    cbnorm_all_kernel<<<NQn * CSn / 32, blk>>>(cbk, gcbn);
    cbnmax_kernel<<<NQn, blk>>>(gcbn, gcbnmax);
    cvt_half_kernel<<<(NQn * CSn * CDn / 8 + 255) / 256, blk>>>(
        cbk, gcbh, NQn * CSn * CDn / 8);
    gemm_kernel<0, 3><<<dim3(RVQn / BN, CSn / BM, NQn), blk>>>(
        cbk, nullptr, oww, nullptr, gwc, nullptr, CDn, RVQn,
        (size_t)CSn * CDn, (size_t)RVQn * CDn, (size_t)CSn * RVQn);

    // 1. input projection: x (and residual copy)
    gemm_kernel<1, 0><<<dim3(RVQn / BN, MTOK / BM), blk>>>(
        z, nullptr, ipw, ipb, gx, gres, DIN, RVQn, 0, 0, 0);

    // 2. RVQ stages
    for (int q = 0; q < NQn; ++q) {
        const float* cbq = cbk + (size_t)q * CSn * CDn;
        gemm_kernel<0, 0><<<dim3(CDn / BN, MTOK / BM), blk>>>(
            gres, nullptr,
            inw + (size_t)q * CDn * RVQn, inb + (size_t)q * CDn,
            genc, nullptr, RVQn, CDn, 0, 0, 0);
        cvt_half_kernel<<<(MTOK * CDn / 8 + 255) / 256, blk>>>(
            genc, gench, MTOK * CDn / 8);
        dist_fp16_kernel<<<dim3(MTOK / BM, CSn / BN), blk, DH_TOTAL>>>(
            gench, gcbh + (size_t)q * CSn * CDn, gcbn + (size_t)q * CSn, gdist);
        float* idxF = writeIdx ? (outF + OUT0 + (size_t)q * MTOK) : nullptr;
        scan_recheck_kernel<<<MTOK / 8, blk>>>(
            gdist, genc, cbq, gcbn + (size_t)q * CSn, gcbnmax + q, gidx, idxF);
        gather_update_kernel<<<(MTOK * 32) / 256, blk>>>(
            gidx, gwc + (size_t)q * CSn * RVQn, owb + (size_t)q * RVQn, gres);
    }

    // 3. output projection on emb = x - res, transposed store
    gemm_kernel<3, 2><<<dim3(DOUT / BN, MTOK / BM), blk>>>(
        gx, gres, opw, opb, outF, nullptr, RVQn, DOUT, 0, 0, 0);
}